// round 3
// baseline (speedup 1.0000x reference)
#include <cuda_runtime.h>
#include <cstdint>

#define KROWS 8192
#define DDIM  256
#define CAP   256
#define NSEL  30
#define NLAB  64
// pass iff (bits >> 9) >= 2^23 - 2^17  <=>  bits >= 0xFC000000  (p = 1/64)
#define THRESH 0xFC000000u

// ---------------- scratch (static device globals; no allocation) ----------------
__device__ float              d_fnorm[KROWS * DDIM];     // normalized features (fp32)
__device__ unsigned long long d_surv[KROWS * CAP];       // survivor keys per row
__device__ int                d_scnt[KROWS];             // survivor counts
__device__ unsigned char      d_lab8[KROWS];             // labels as u8
__device__ int                d_counts[NLAB];
__device__ int                d_offsets[NLAB];
__device__ int                d_grows[KROWS];            // rows grouped by label (deterministic order)
__device__ float              d_num[KROWS];              // per-row numerator
__device__ float              d_negsum[KROWS];           // per-row negative sum
__device__ int                d_is64;                    // labels dtype flag

// ---------------- threefry2x32-20, key = (0, 42) ----------------
__device__ __forceinline__ uint32_t rotl32(uint32_t x, int r) {
    return (x << r) | (x >> (32 - r));
}

__device__ __forceinline__ void threefry(uint32_t i0, uint32_t i1,
                                         uint32_t& o0, uint32_t& o1) {
    const uint32_t ks0 = 0u, ks1 = 42u, ks2 = 0x1BD11BF0u;  // 0 ^ 42 ^ 0x1BD11BDA
    uint32_t x0 = i0 + ks0;
    uint32_t x1 = i1 + ks1;
#define TF_RND(r) { x0 += x1; x1 = rotl32(x1, (r)) ^ x0; }
    TF_RND(13) TF_RND(15) TF_RND(26) TF_RND(6)
    x0 += ks1; x1 += ks2 + 1u;
    TF_RND(17) TF_RND(29) TF_RND(16) TF_RND(24)
    x0 += ks2; x1 += ks0 + 2u;
    TF_RND(13) TF_RND(15) TF_RND(26) TF_RND(6)
    x0 += ks0; x1 += ks1 + 3u;
    TF_RND(17) TF_RND(29) TF_RND(16) TF_RND(24)
    x0 += ks1; x1 += ks2 + 4u;
    TF_RND(13) TF_RND(15) TF_RND(26) TF_RND(6)
    x0 += ks2; x1 += ks0 + 5u;
#undef TF_RND
    o0 = x0; o1 = x1;
}

// ---------------- setup kernels ----------------
__global__ void k_init() {
    int i = blockIdx.x * blockDim.x + threadIdx.x;
    if (i < NLAB)  d_counts[i] = 0;
    if (i < KROWS) d_scnt[i] = 0;
}

// Detect labels dtype using ONLY the first 8192 int32 words (safe for both
// int32[8192] and int64[8192] buffers). int64 little-endian with values in
// [0,64) has the high word of every element == 0; int32 labels make the odd
// words be label values (all-zero probability (1/64)^31 ~ 0).
__global__ void k_detect(const int* __restrict__ raw) {
    if (threadIdx.x == 0 && blockIdx.x == 0) {
        int odd_nonzero = 0;
        for (int p = 0; p < 32; p++) odd_nonzero |= raw[2 * p + 1];
        d_is64 = (odd_nonzero == 0) ? 1 : 0;
    }
}

__global__ void k_hist(const int* __restrict__ raw) {
    int i = blockIdx.x * blockDim.x + threadIdx.x;
    if (i < KROWS) {
        int l = d_is64 ? raw[2 * i] : raw[i];
        l &= (NLAB - 1);                      // safety clamp: no OOB ever
        d_lab8[i] = (unsigned char)l;
        atomicAdd(&d_counts[l], 1);
    }
}

__global__ void k_offsets() {
    if (threadIdx.x == 0 && blockIdx.x == 0) {
        int acc = 0;
        for (int i = 0; i < NLAB; i++) { d_offsets[i] = acc; acc += d_counts[i]; }
    }
}

// one warp per label; deterministic ballot-compaction
__global__ void k_group() {
    int w = (blockIdx.x * blockDim.x + threadIdx.x) >> 5;
    int lane = threadIdx.x & 31;
    if (w >= NLAB) return;
    int out = d_offsets[w];
    for (int base = 0; base < KROWS; base += 32) {
        int lab = (int)d_lab8[base + lane];
        unsigned m = __ballot_sync(0xffffffffu, lab == w);
        if (lab == w) {
            int pos = out + __popc(m & ((1u << lane) - 1u));
            d_grows[pos] = base + lane;
        }
        out += __popc(m);
    }
}

// warp per row: L2 normalize
__global__ void k_norm(const float* __restrict__ x) {
    int w = (blockIdx.x * blockDim.x + threadIdx.x) >> 5;
    int lane = threadIdx.x & 31;
    if (w >= KROWS) return;
    float v[8]; float ss = 0.f;
#pragma unroll
    for (int k = 0; k < 8; k++) {
        v[k] = x[w * DDIM + lane + 32 * k];
        ss += v[k] * v[k];
    }
#pragma unroll
    for (int o = 16; o; o >>= 1) ss += __shfl_xor_sync(0xffffffffu, ss, o);
    float sc = 1.0f / fmaxf(sqrtf(ss), 1e-12f);
#pragma unroll
    for (int k = 0; k < 8; k++) d_fnorm[w * DDIM + lane + 32 * k] = v[k] * sc;
}

// ---------------- phase 1: threefry sweep + threshold filter ----------------
// JAX partitionable threefry (default since 0.4.36):
//   counter = iota(u64, 2^26); x = (hi32, lo32) = (0, flat_idx) for our size
//   bits32[flat] = out0 ^ out1
// warp per row; 256 column-iterations of 32 lanes.
__global__ void k_phase1() {
    __shared__ unsigned char slab[KROWS];
    int tid = threadIdx.x;
    for (int i = tid; i < KROWS; i += blockDim.x) slab[i] = d_lab8[i];
    __syncthreads();

    int row  = (blockIdx.x * blockDim.x + tid) >> 5;   // 0..8191
    int lane = tid & 31;
    unsigned char lr = slab[row];
    unsigned base = (unsigned)row * 8192u;

    for (int k = 0; k < 256; k++) {
        unsigned c = (unsigned)lane + 32u * (unsigned)k;
        uint32_t y0, y1;
        threefry(0u, base + c, y0, y1);
        uint32_t bits = y0 ^ y1;
        if (bits >= THRESH && slab[c] != lr) {
            int idx = atomicAdd(&d_scnt[row], 1);
            if (idx < CAP)
                d_surv[row * CAP + idx] =
                    (((unsigned long long)(bits >> 9)) << 13) | (unsigned long long)(8191u - c);
        }
    }
}

// ---------------- phase 2: exact top-30 by key; gather dots; sum exp ----------------
__global__ void k_phase2() {
    int row  = (blockIdx.x * blockDim.x + threadIdx.x) >> 5;
    int lane = threadIdx.x & 31;
    if (row >= KROWS) return;

    int n = min(d_scnt[row], CAP);
    unsigned long long e[CAP / 32];
#pragma unroll
    for (int k = 0; k < CAP / 32; k++) {
        int idx = lane + 32 * k;
        e[k] = (idx < n) ? d_surv[row * CAP + idx] : 0ULL;
    }
    float fi[8];
#pragma unroll
    for (int k = 0; k < 8; k++) fi[k] = d_fnorm[row * DDIM + lane + 32 * k];

    float acc = 0.f;
    for (int s = 0; s < NSEL; s++) {
        unsigned long long lm = 0ULL; int lk = -1;
#pragma unroll
        for (int k = 0; k < CAP / 32; k++)
            if (e[k] > lm) { lm = e[k]; lk = k; }
        unsigned long long wm = lm;
#pragma unroll
        for (int o = 16; o; o >>= 1) {
            unsigned long long other = __shfl_xor_sync(0xffffffffu, wm, o);
            if (other > wm) wm = other;
        }
        if (wm == 0ULL) break;                 // < 30 survivors (practically impossible)
        if (lk >= 0 && lm == wm) e[lk] = 0ULL; // unique keys -> exactly one lane clears

        int col = 8191 - (int)(wm & 0x1FFFULL);
        const float* fc = &d_fnorm[col * DDIM];
        float p = 0.f;
#pragma unroll
        for (int k = 0; k < 8; k++) p += fi[k] * fc[lane + 32 * k];
#pragma unroll
        for (int o = 16; o; o >>= 1) p += __shfl_xor_sync(0xffffffffu, p, o);
        acc += __expf(10.f * p - 10.f);        // exp(sim/T - 10); shift cancels in ratio
    }
    if (lane == 0) d_negsum[row] = acc;
}

// ---------------- phase 3: top-6 same-label sims; numerator ----------------
// warp per anchor, anchors in grouped order so the 8 warps of a CTA share L1 on group cols
__global__ void k_phase3() {
    int gi   = (blockIdx.x * blockDim.x + threadIdx.x) >> 5;
    int lane = threadIdx.x & 31;
    if (gi >= KROWS) return;

    int row = d_grows[gi];
    int lbl = (int)d_lab8[row];
    int off = d_offsets[lbl];
    int cnt = d_counts[lbl];

    float fi[8];
#pragma unroll
    for (int k = 0; k < 8; k++) fi[k] = d_fnorm[row * DDIM + lane + 32 * k];

    float v[6];
#pragma unroll
    for (int k = 0; k < 6; k++) v[k] = -3.0e38f;

    for (int j = 0; j < cnt; j++) {
        int col = d_grows[off + j];
        if (col == row) continue;
        const float* fc = &d_fnorm[col * DDIM];
        float p = 0.f;
#pragma unroll
        for (int k = 0; k < 8; k++) p += fi[k] * fc[lane + 32 * k];
#pragma unroll
        for (int o = 16; o; o >>= 1) p += __shfl_xor_sync(0xffffffffu, p, o);
        // keep 6 largest (descending insertion chain)
        float a = p;
#pragma unroll
        for (int k = 0; k < 6; k++) {
            float hi = fmaxf(v[k], a);
            float lo = fminf(v[k], a);
            v[k] = hi; a = lo;
        }
    }

    int npos = cnt - 1;
    int m = min(npos, 6);
    float num = 0.f;
#pragma unroll
    for (int k = 0; k < 6; k++)
        if (k < m) num += __expf(10.f * v[k] - 10.f);
    if (lane == 0) d_num[row] = num;
}

// ---------------- final reduction (deterministic fixed-order) ----------------
__global__ void k_reduce(float* __restrict__ out) {
    __shared__ float sm[256];
    int t = threadIdx.x;
    float a = 0.f;
    for (int i = t; i < KROWS; i += 256) {
        float num = d_num[i];
        float den = num + d_negsum[i];
        float r = num / den;
        r = fmaxf(r, 1e-8f);
        a += -__logf(r);
    }
    sm[t] = a;
    __syncthreads();
    for (int s = 128; s; s >>= 1) {
        if (t < s) sm[t] += sm[t + s];
        __syncthreads();
    }
    if (t == 0) out[0] = sm[0] * (1.0f / 8192.0f);
}

// ---------------- launch ----------------
extern "C" void kernel_launch(void* const* d_in, const int* in_sizes, int n_in,
                              void* d_out, int out_size) {
    const float* features = (const float*)d_in[0];
    const int*   labraw   = (const int*)d_in[1];
    float* out = (float*)d_out;

    k_init   <<<32, 256>>>();
    k_detect <<<1, 32>>>(labraw);
    k_hist   <<<32, 256>>>(labraw);
    k_offsets<<<1, 32>>>();
    k_group  <<<2, 1024>>>();
    k_norm   <<<1024, 256>>>(features);
    k_phase1 <<<1024, 256>>>();
    k_phase2 <<<1024, 256>>>();
    k_phase3 <<<1024, 256>>>();
    k_reduce <<<1, 256>>>(out);
}

// round 4
// speedup vs baseline: 1.0672x; 1.0672x over previous
#include <cuda_runtime.h>
#include <cstdint>

#define KROWS 8192
#define DDIM  256
#define CAP   256
#define NSEL  30
#define NLAB  64
// pass iff bits >= 2^32 - 2^26  (p = 1/64); key = (bits>>9)<<13 | (8191-col)
#define THRESH 0xFC000000u

typedef unsigned long long u64;

// ---------------- scratch (static device globals; no allocation) ----------------
__device__ float         d_fnorm[KROWS * DDIM];
__device__ unsigned char d_lab8[KROWS];
__device__ int           d_counts[NLAB];
__device__ int           d_offsets[NLAB];
__device__ int           d_grows[KROWS];
__device__ float         d_num[KROWS];
__device__ float         d_negsum[KROWS];

// ---------------- threefry2x32-20, key = (0, 42) ----------------
__device__ __forceinline__ uint32_t rotl32(uint32_t x, int r) {
    return __funnelshift_l(x, x, r);
}

__device__ __forceinline__ uint32_t threefry_xor(uint32_t i0, uint32_t i1) {
    const uint32_t ks0 = 0u, ks1 = 42u, ks2 = 0x1BD11BF0u;  // 0 ^ 42 ^ 0x1BD11BDA
    uint32_t x0 = i0 + ks0;
    uint32_t x1 = i1 + ks1;
#define TF_RND(r) { x0 += x1; x1 = rotl32(x1, (r)) ^ x0; }
    TF_RND(13) TF_RND(15) TF_RND(26) TF_RND(6)
    x0 += ks1; x1 += ks2 + 1u;
    TF_RND(17) TF_RND(29) TF_RND(16) TF_RND(24)
    x0 += ks2; x1 += ks0 + 2u;
    TF_RND(13) TF_RND(15) TF_RND(26) TF_RND(6)
    x0 += ks0; x1 += ks1 + 3u;
    TF_RND(17) TF_RND(29) TF_RND(16) TF_RND(24)
    x0 += ks1; x1 += ks2 + 4u;
    TF_RND(13) TF_RND(15) TF_RND(26) TF_RND(6)
    x0 += ks2; x1 += ks0 + 5u;
#undef TF_RND
    return x0 ^ x1;
}

// ---------------- setup: dtype detect + labels + hist + offsets + group ----------------
__global__ void k_setup(const int* __restrict__ raw) {
    __shared__ int s_is64;
    __shared__ int s_cnt[NLAB];
    __shared__ int s_off[NLAB];
    __shared__ unsigned char s_lab[KROWS];
    int t = threadIdx.x;                      // 1024 threads

    if (t == 0) {
        // int64 LE labels in [0,64): every high word is 0. For int32 labels the
        // odd words are label values; all-zero prob (1/64)^31 ~ 0. Reads only
        // the first 8192 int32 words (safe for both layouts).
        int odd = 0;
        for (int p = 0; p < 32; p++) odd |= raw[2 * p + 1];
        s_is64 = (odd == 0);
    }
    if (t < NLAB) s_cnt[t] = 0;
    __syncthreads();
    int is64 = s_is64;
    for (int i = t; i < KROWS; i += 1024) {
        int l = (is64 ? raw[2 * i] : raw[i]) & (NLAB - 1);
        s_lab[i] = (unsigned char)l;
        d_lab8[i] = (unsigned char)l;
        atomicAdd(&s_cnt[l], 1);
    }
    __syncthreads();
    if (t == 0) {
        int acc = 0;
        for (int i = 0; i < NLAB; i++) {
            s_off[i] = acc; d_offsets[i] = acc; d_counts[i] = s_cnt[i];
            acc += s_cnt[i];
        }
    }
    __syncthreads();
    // deterministic ballot-compaction; warp w handles labels w, w+32
    int w = t >> 5, lane = t & 31;
    for (int li = w; li < NLAB; li += 32) {
        int out = s_off[li];
        for (int base = 0; base < KROWS; base += 32) {
            int lab = (int)s_lab[base + lane];
            unsigned m = __ballot_sync(0xffffffffu, lab == li);
            if (lab == li)
                d_grows[out + __popc(m & ((1u << lane) - 1u))] = base + lane;
            out += __popc(m);
        }
    }
}

// ---------------- L2 normalize (warp per row) ----------------
__global__ void k_norm(const float* __restrict__ x) {
    int w = (blockIdx.x * blockDim.x + threadIdx.x) >> 5;
    int lane = threadIdx.x & 31;
    if (w >= KROWS) return;
    float v[8]; float ss = 0.f;
#pragma unroll
    for (int k = 0; k < 8; k++) {
        v[k] = x[w * DDIM + lane + 32 * k];
        ss += v[k] * v[k];
    }
#pragma unroll
    for (int o = 16; o; o >>= 1) ss += __shfl_xor_sync(0xffffffffu, ss, o);
    float sc = 1.0f / fmaxf(sqrtf(ss), 1e-12f);
#pragma unroll
    for (int k = 0; k < 8; k++) d_fnorm[w * DDIM + lane + 32 * k] = v[k] * sc;
}

// ---------------- mega: threefry sweep + top-30 negatives + top-6 positives ----------------
// warp per row; 8 warps/CTA; 1024 CTAs.
__global__ __launch_bounds__(256) void k_mega() {
    __shared__ unsigned char slab[KROWS];
    __shared__ u64 s_surv[8][CAP];
    int tid = threadIdx.x;
    for (int i = tid; i < KROWS; i += blockDim.x) slab[i] = d_lab8[i];
    __syncthreads();

    int wl   = tid >> 5;
    int lane = tid & 31;
    int row  = blockIdx.x * 8 + wl;
    unsigned char lr = slab[row];
    unsigned base = (unsigned)row * 8192u;
    u64* sv = s_surv[wl];
    int cnt = 0;

    // ---- phase 1: threefry + threshold filter, ballot compaction ----
#pragma unroll 4
    for (int k = 0; k < 256; k++) {
        unsigned c = (unsigned)lane + 32u * (unsigned)k;
        uint32_t bits = threefry_xor(0u, base + c);
        bool pass = (bits >= THRESH) && (slab[c] != lr);
        unsigned m = __ballot_sync(0xffffffffu, pass);
        if (pass) {
            int idx = cnt + __popc(m & ((1u << lane) - 1u));
            if (idx < CAP)
                sv[idx] = (((u64)(bits >> 9)) << 13) | (u64)(8191u - c);
        }
        cnt += __popc(m);
    }
    cnt = min(cnt, CAP);
    __syncwarp();

    // ---- phase 2: exact top-30 by key; gather dots; negative sum ----
    u64 e[CAP / 32];
#pragma unroll
    for (int k = 0; k < CAP / 32; k++) {
        int idx = lane + 32 * k;
        e[k] = (idx < cnt) ? sv[idx] : 0ULL;
    }
    float fi[8];
#pragma unroll
    for (int k = 0; k < 8; k++) fi[k] = d_fnorm[row * DDIM + lane + 32 * k];

    float acc = 0.f;
    for (int s = 0; s < NSEL; s++) {
        u64 lm = 0ULL; int lk = -1;
#pragma unroll
        for (int k = 0; k < CAP / 32; k++)
            if (e[k] > lm) { lm = e[k]; lk = k; }
        u64 wm = lm;
#pragma unroll
        for (int o = 16; o; o >>= 1) {
            u64 other = __shfl_xor_sync(0xffffffffu, wm, o);
            if (other > wm) wm = other;
        }
        if (wm == 0ULL) break;                 // < 30 survivors (practically impossible)
        if (lk >= 0 && lm == wm) e[lk] = 0ULL; // unique keys: exactly one lane clears

        int col = 8191 - (int)(wm & 0x1FFFULL);
        const float* fc = &d_fnorm[col * DDIM];
        float p = 0.f;
#pragma unroll
        for (int k = 0; k < 8; k++) p += fi[k] * fc[lane + 32 * k];
#pragma unroll
        for (int o = 16; o; o >>= 1) p += __shfl_xor_sync(0xffffffffu, p, o);
        acc += __expf(10.f * p - 10.f);        // exp(sim/T - max); shift cancels in ratio
    }
    if (lane == 0) d_negsum[row] = acc;

    // ---- phase 3: top-6 same-label sims for anchor d_grows[row] ----
    int anchor = d_grows[row];
    int lbl = (int)slab[anchor];
    int off = d_offsets[lbl];
    int gcnt = d_counts[lbl];

#pragma unroll
    for (int k = 0; k < 8; k++) fi[k] = d_fnorm[anchor * DDIM + lane + 32 * k];

    float v[6];
#pragma unroll
    for (int k = 0; k < 6; k++) v[k] = -3.0e38f;

    for (int j = 0; j < gcnt; j++) {
        int col = d_grows[off + j];
        if (col == anchor) continue;
        const float* fc = &d_fnorm[col * DDIM];
        float p = 0.f;
#pragma unroll
        for (int k = 0; k < 8; k++) p += fi[k] * fc[lane + 32 * k];
#pragma unroll
        for (int o = 16; o; o >>= 1) p += __shfl_xor_sync(0xffffffffu, p, o);
        float a = p;                            // keep 6 largest
#pragma unroll
        for (int k = 0; k < 6; k++) {
            float hi = fmaxf(v[k], a);
            float lo = fminf(v[k], a);
            v[k] = hi; a = lo;
        }
    }

    int m = min(gcnt - 1, 6);
    float num = 0.f;
#pragma unroll
    for (int k = 0; k < 6; k++)
        if (k < m) num += __expf(10.f * v[k] - 10.f);
    if (lane == 0) d_num[anchor] = num;
}

// ---------------- final reduction (deterministic fixed-order) ----------------
__global__ void k_reduce(float* __restrict__ out) {
    __shared__ float sm[256];
    int t = threadIdx.x;
    float a = 0.f;
    for (int i = t; i < KROWS; i += 256) {
        float num = d_num[i];
        float den = num + d_negsum[i];
        float r = fmaxf(num / den, 1e-8f);
        a += -__logf(r);
    }
    sm[t] = a;
    __syncthreads();
    for (int s = 128; s; s >>= 1) {
        if (t < s) sm[t] += sm[t + s];
        __syncthreads();
    }
    if (t == 0) out[0] = sm[0] * (1.0f / 8192.0f);
}

// ---------------- launch ----------------
extern "C" void kernel_launch(void* const* d_in, const int* in_sizes, int n_in,
                              void* d_out, int out_size) {
    const float* features = (const float*)d_in[0];
    const int*   labraw   = (const int*)d_in[1];
    float* out = (float*)d_out;

    k_setup <<<1, 1024>>>(labraw);
    k_norm  <<<1024, 256>>>(features);
    k_mega  <<<1024, 256>>>();
    k_reduce<<<1, 256>>>(out);
}

// round 5
// speedup vs baseline: 1.2074x; 1.1314x over previous
#include <cuda_runtime.h>
#include <cstdint>

#define KROWS 8192
#define DDIM  256
#define CAP   256
#define NSEL  30
#define NLAB  64
// pass iff bits >= 2^32 - 2^26  (p = 1/64)
#define THRESH 0xFC000000u

typedef unsigned long long u64;

// ---------------- scratch (static device globals; no allocation) ----------------
__device__ __align__(16) float         d_fnorm[KROWS * DDIM];
__device__ __align__(16) unsigned char d_lab8[KROWS];
__device__ int   d_counts[NLAB];
__device__ int   d_offsets[NLAB];
__device__ int   d_grows[KROWS];
__device__ float d_num[KROWS];
__device__ float d_negsum[KROWS];
__device__ float d_partial[32];

// ---------------- threefry2x32-20, key = (0, 42), partitionable out0^out1 ----------------
__device__ __forceinline__ uint32_t rotl32(uint32_t x, int r) {
    return __funnelshift_l(x, x, r);
}

__device__ __forceinline__ uint32_t threefry_xor(uint32_t i0, uint32_t i1) {
    const uint32_t ks0 = 0u, ks1 = 42u, ks2 = 0x1BD11BF0u;  // 0 ^ 42 ^ 0x1BD11BDA
    uint32_t x0 = i0 + ks0;
    uint32_t x1 = i1 + ks1;
#define TF_RND(r) { x0 += x1; x1 = rotl32(x1, (r)) ^ x0; }
    TF_RND(13) TF_RND(15) TF_RND(26) TF_RND(6)
    x0 += ks1; x1 += ks2 + 1u;
    TF_RND(17) TF_RND(29) TF_RND(16) TF_RND(24)
    x0 += ks2; x1 += ks0 + 2u;
    TF_RND(13) TF_RND(15) TF_RND(26) TF_RND(6)
    x0 += ks0; x1 += ks1 + 3u;
    TF_RND(17) TF_RND(29) TF_RND(16) TF_RND(24)
    x0 += ks1; x1 += ks2 + 4u;
    TF_RND(13) TF_RND(15) TF_RND(26) TF_RND(6)
    x0 += ks2; x1 += ks0 + 5u;
#undef TF_RND
    return x0 ^ x1;
}

// ---------------- setup: dtype detect + labels + hist + offsets + group ----------------
__global__ void k_setup(const int* __restrict__ raw) {
    __shared__ int s_is64;
    __shared__ int s_cnt[NLAB];
    __shared__ int s_off[NLAB];
    __shared__ unsigned char s_lab[KROWS];
    int t = threadIdx.x;                      // 1024 threads

    if (t == 0) {
        // int64 LE labels in [0,64): every high word is 0; for int32 labels the
        // odd words are labels (all-zero prob (1/64)^31 ~ 0). Reads only the
        // first 8192 int32 words (safe for both layouts).
        int odd = 0;
        for (int p = 0; p < 32; p++) odd |= raw[2 * p + 1];
        s_is64 = (odd == 0);
    }
    if (t < NLAB) s_cnt[t] = 0;
    __syncthreads();
    int is64 = s_is64;
    for (int i = t; i < KROWS; i += 1024) {
        int l = (is64 ? raw[2 * i] : raw[i]) & (NLAB - 1);
        s_lab[i] = (unsigned char)l;
        d_lab8[i] = (unsigned char)l;
        atomicAdd(&s_cnt[l], 1);
    }
    __syncthreads();
    if (t == 0) {
        int acc = 0;
        for (int i = 0; i < NLAB; i++) {
            s_off[i] = acc; d_offsets[i] = acc; d_counts[i] = s_cnt[i];
            acc += s_cnt[i];
        }
    }
    __syncthreads();
    // deterministic ballot-compaction; warp w handles labels w, w+32
    int w = t >> 5, lane = t & 31;
    for (int li = w; li < NLAB; li += 32) {
        int out = s_off[li];
        for (int base = 0; base < KROWS; base += 32) {
            int lab = (int)s_lab[base + lane];
            unsigned m = __ballot_sync(0xffffffffu, lab == li);
            if (lab == li)
                d_grows[out + __popc(m & ((1u << lane) - 1u))] = base + lane;
            out += __popc(m);
        }
    }
}

// ---------------- L2 normalize (warp per row, float4) ----------------
__global__ void k_norm(const float* __restrict__ x) {
    int w = (blockIdx.x * blockDim.x + threadIdx.x) >> 5;
    int lane = threadIdx.x & 31;
    if (w >= KROWS) return;
    const float4* x4 = (const float4*)(x) + w * 64;
    float4* o4 = (float4*)(d_fnorm) + w * 64;
    float4 a = x4[lane], b = x4[lane + 32];
    float ss = a.x * a.x + a.y * a.y + a.z * a.z + a.w * a.w
             + b.x * b.x + b.y * b.y + b.z * b.z + b.w * b.w;
#pragma unroll
    for (int o = 16; o; o >>= 1) ss += __shfl_xor_sync(0xffffffffu, ss, o);
    float sc = 1.0f / fmaxf(sqrtf(ss), 1e-12f);
    a.x *= sc; a.y *= sc; a.z *= sc; a.w *= sc;
    b.x *= sc; b.y *= sc; b.z *= sc; b.w *= sc;
    o4[lane] = a; o4[lane + 32] = b;
}

// warp dot between preloaded (a0,a1) and row `col` of d_fnorm
__device__ __forceinline__ float warp_dot(float4 a0, float4 a1, int col, int lane) {
    const float4* c4 = (const float4*)(d_fnorm) + col * 64;
    float4 b0 = __ldg(&c4[lane]);
    float4 b1 = __ldg(&c4[lane + 32]);
    float p = a0.x * b0.x + a0.y * b0.y + a0.z * b0.z + a0.w * b0.w
            + a1.x * b1.x + a1.y * b1.y + a1.z * b1.z + a1.w * b1.w;
#pragma unroll
    for (int o = 16; o; o >>= 1) p += __shfl_xor_sync(0xffffffffu, p, o);
    return p;
}

// ---------------- mega: threefry sweep + top-30 negatives + top-6 positives ----------------
// warp per row; 8 warps/CTA; 1024 CTAs.
__global__ __launch_bounds__(256) void k_mega() {
    __shared__ unsigned s_mask[8][256];   // diff-label bitmask per CTA-row
    __shared__ unsigned s_surv[8][CAP];   // u32 survivor keys
    int tid  = threadIdx.x;
    int wl   = tid >> 5;
    int lane = tid & 31;
    int row0 = blockIdx.x * 8;

    // build diff-label masks: i = r*256 + k; word k covers cols [32k, 32k+32)
    const unsigned* lw = (const unsigned*)d_lab8;
    for (int i = tid; i < 8 * 256; i += 256) {
        int r = i >> 8, k = i & 255;
        unsigned lr4 = (unsigned)d_lab8[row0 + r] * 0x01010101u;
        unsigned mk = 0;
#pragma unroll
        for (int w = 0; w < 8; w++) {
            unsigned d = __vcmpne4(lw[8 * k + w], lr4);
            mk |= ((((d & 0x01010101u) * 0x01020408u) >> 24) & 0xFu) << (4 * w);
        }
        s_mask[r][k] = mk;
    }
    __syncthreads();

    int row = row0 + wl;
    unsigned base = (unsigned)row * 8192u;
    unsigned* mrow = s_mask[wl];
    unsigned* sv = s_surv[wl];
    int cnt = 0;

    // ---- phase 1: threefry + threshold + mask, ballot compaction ----
#pragma unroll 4
    for (int k = 0; k < 256; k++) {
        unsigned c = (unsigned)lane + 32u * (unsigned)k;
        uint32_t bits = threefry_xor(0u, base + c);
        unsigned m = __ballot_sync(0xffffffffu, bits >= THRESH) & mrow[k];
        if ((m >> lane) & 1u) {
            int idx = cnt + __popc(m & ((1u << lane) - 1u));
            if (idx < CAP)
                sv[idx] = (((bits >> 9) - 0x7E0000u) << 13) | (8191u - c);
        }
        cnt += __popc(m);
    }
    cnt = min(cnt, CAP);
    __syncwarp();

    // ---- phase 2: exact top-30 by u32 key; gather dots; negative sum ----
    unsigned e[CAP / 32];
#pragma unroll
    for (int k = 0; k < CAP / 32; k++) {
        int idx = lane + 32 * k;
        e[k] = (idx < cnt) ? sv[idx] : 0u;
    }
    const float4* f4 = (const float4*)(d_fnorm) + row * 64;
    float4 a0 = f4[lane], a1 = f4[lane + 32];

    float acc = 0.f;
    for (int s = 0; s < NSEL; s++) {
        unsigned lm = 0u; int lk = -1;
#pragma unroll
        for (int k = 0; k < CAP / 32; k++)
            if (e[k] > lm) { lm = e[k]; lk = k; }
        unsigned wm = lm;
#pragma unroll
        for (int o = 16; o; o >>= 1)
            wm = max(wm, __shfl_xor_sync(0xffffffffu, wm, o));
        if (wm == 0u) break;                  // < 30 survivors (practically impossible)
        if (lk >= 0 && lm == wm) e[lk] = 0u;  // unique keys: exactly one lane clears

        int col = 8191 - (int)(wm & 0x1FFFu);
        float p = warp_dot(a0, a1, col, lane);
        acc += __expf(10.f * p - 10.f);       // exp(sim/T - max); shift cancels in ratio
    }
    if (lane == 0) d_negsum[row] = acc;

    // align warps so the CTA's 8 same-group anchors stream cols together (L1 reuse)
    __syncthreads();

    // ---- phase 3: top-6 same-label sims for anchor d_grows[row] ----
    int anchor = d_grows[row];
    int lbl = (int)d_lab8[anchor];
    int off = d_offsets[lbl];
    int gcnt = d_counts[lbl];

    const float4* g4 = (const float4*)(d_fnorm) + anchor * 64;
    a0 = g4[lane]; a1 = g4[lane + 32];

    float v[6];
#pragma unroll
    for (int k = 0; k < 6; k++) v[k] = -3.0e38f;

    for (int j = 0; j < gcnt; j++) {
        int col = d_grows[off + j];
        if (col == anchor) continue;
        float p = warp_dot(a0, a1, col, lane);
        float a = p;                          // keep 6 largest
#pragma unroll
        for (int k = 0; k < 6; k++) {
            float hi = fmaxf(v[k], a);
            float lo = fminf(v[k], a);
            v[k] = hi; a = lo;
        }
    }

    int m = min(gcnt - 1, 6);
    float num = 0.f;
#pragma unroll
    for (int k = 0; k < 6; k++)
        if (k < m) num += __expf(10.f * v[k] - 10.f);
    if (lane == 0) d_num[anchor] = num;
}

// ---------------- two-stage deterministic reduction ----------------
__global__ void k_red1() {
    __shared__ float sm[256];
    int i = blockIdx.x * 256 + threadIdx.x;   // 32 CTAs x 256 = 8192
    float num = d_num[i];
    float den = num + d_negsum[i];
    float r = fmaxf(num / den, 1e-8f);
    sm[threadIdx.x] = -__logf(r);
    __syncthreads();
    for (int s = 128; s; s >>= 1) {
        if (threadIdx.x < s) sm[threadIdx.x] += sm[threadIdx.x + s];
        __syncthreads();
    }
    if (threadIdx.x == 0) d_partial[blockIdx.x] = sm[0];
}

__global__ void k_red2(float* __restrict__ out) {
    int lane = threadIdx.x;
    float a = d_partial[lane];                // 32 values
#pragma unroll
    for (int o = 16; o; o >>= 1) a += __shfl_xor_sync(0xffffffffu, a, o);
    if (lane == 0) out[0] = a * (1.0f / 8192.0f);
}

// ---------------- launch ----------------
extern "C" void kernel_launch(void* const* d_in, const int* in_sizes, int n_in,
                              void* d_out, int out_size) {
    const float* features = (const float*)d_in[0];
    const int*   labraw   = (const int*)d_in[1];
    float* out = (float*)d_out;

    k_setup<<<1, 1024>>>(labraw);
    k_norm <<<1024, 256>>>(features);
    k_mega <<<1024, 256>>>();
    k_red1 <<<32, 256>>>();
    k_red2 <<<1, 32>>>(out);
}